// round 2
// baseline (speedup 1.0000x reference)
#include <cuda_runtime.h>

// ---------------- device scratch (allocation-free: __device__ globals) -------
__device__ float g_stat1;            // conv1 input stat (scalar, C_in=1)
__device__ float g_stat2[64];        // conv2 input stat per channel
__device__ float g_stat3[1024];      // linear input stat per feature
__device__ float g_w1[1600];         // conv1 effective weights (64,1,5,5)
__device__ float g_b1[64];
__device__ float g_w2p[64 * 64 * 28]; // conv2 eff weights padded: (co*64+ci)*28 + j, j<25
__device__ float g_b2[64];
__device__ float g_wl[10240];        // linear eff weights (10,1024)
__device__ float g_bl[10];
__device__ float g_h1[2048 * 64 * 144]; // pooled conv1 output (N,64,12,12)
__device__ float g_h2[2048 * 1024];     // pooled conv2 output, flattened (N,1024)

// ---------------- helpers ----------------------------------------------------
__device__ __forceinline__ float scinol(float p0, float S2, float G, float eta,
                                        float M, bool cond) {
    float denom = sqrtf(S2 + M * M);
    float theta = fminf(fmaxf(G / denom, -1.0f), 1.0f);
    float upd = cond ? theta / (2.0f * denom) * eta : 0.0f;
    return p0 + upd;
}

__device__ __forceinline__ unsigned long long pk2(float v) {
    unsigned long long r;
    asm("mov.b64 %0, {%1, %2};" : "=l"(r) : "f"(v), "f"(v));
    return r;
}
__device__ __forceinline__ void fma2(unsigned long long& d, unsigned long long a,
                                     unsigned long long b) {
    asm("fma.rn.f32x2 %0, %1, %2, %0;" : "+l"(d) : "l"(a), "l"(b));
}
__device__ __forceinline__ void upk2(unsigned long long v, float& lo, float& hi) {
    asm("mov.b64 {%0, %1}, %2;" : "=f"(lo), "=f"(hi) : "l"(v));
}

// ---------------- kernel 0: zero stat accumulators ---------------------------
__global__ void zero_stats_kernel() {
    int i = threadIdx.x;
    if (i == 0) g_stat1 = 0.0f;
    if (i < 64) g_stat2[i] = 0.0f;
    if (i < 1024) g_stat3[i] = 0.0f;
}

// ---------------- kernel 1: stat1 = mean_n max_hw |x| ------------------------
__global__ void stat1_kernel(const float* __restrict__ x) {
    int n = blockIdx.x;
    const float* xs = x + n * 784;
    float m = 0.0f;
    for (int i = threadIdx.x; i < 784; i += 256) m = fmaxf(m, fabsf(xs[i]));
    __shared__ float red[8];
    #pragma unroll
    for (int o = 16; o; o >>= 1) m = fmaxf(m, __shfl_xor_sync(0xffffffffu, m, o));
    if ((threadIdx.x & 31) == 0) red[threadIdx.x >> 5] = m;
    __syncthreads();
    if (threadIdx.x < 8) {
        m = red[threadIdx.x];
        #pragma unroll
        for (int o = 4; o; o >>= 1) m = fmaxf(m, __shfl_xor_sync(0x000000ffu, m, o));
        if (threadIdx.x == 0) atomicAdd(&g_stat1, m * (1.0f / 2048.0f));
    }
}

// ---------------- kernel 2: conv1 effective params ---------------------------
__global__ void w1_kernel(const float* __restrict__ w0, const float* __restrict__ wS2,
                          const float* __restrict__ wG, const float* __restrict__ weta,
                          const float* __restrict__ wM, const float* __restrict__ b0,
                          const float* __restrict__ bS2, const float* __restrict__ bG,
                          const float* __restrict__ beta) {
    int i = blockIdx.x * 256 + threadIdx.x;
    if (i < 1600) {
        float M = fmaxf(g_stat1, wM[0]);  // C_in = 1
        g_w1[i] = scinol(w0[i], wS2[i], wG[i], weta[i], M, wG[i] != 0.0f);
    } else if (i < 1664) {
        int j = i - 1600;
        g_b1[j] = scinol(b0[j], bS2[j], bG[j], beta[j], 1.0f, bG[j] != 0.0f);
    }
}

// ---------------- kernel 3: conv1 + relu + pool + stat2 ----------------------
__global__ void __launch_bounds__(256) conv1_kernel(const float* __restrict__ x) {
    __shared__ float xs[784];
    __shared__ float ws[1600];
    __shared__ float bs[64];
    __shared__ unsigned int smax[64];
    int n = blockIdx.x;
    const float* xp = x + n * 784;
    for (int i = threadIdx.x; i < 784; i += 256) xs[i] = xp[i];
    for (int i = threadIdx.x; i < 1600; i += 256) ws[i] = g_w1[i];
    if (threadIdx.x < 64) { bs[threadIdx.x] = g_b1[threadIdx.x]; smax[threadIdx.x] = 0u; }
    __syncthreads();

    #pragma unroll 1
    for (int it = 0; it < 3; it++) {
        int task = threadIdx.x + it * 256;   // 768 tasks = 64 ch * 12 pooled rows
        int c = task / 12;
        int py = task % 12;
        float a0[24], a1[24];
        float b = bs[c];
        #pragma unroll
        for (int j = 0; j < 24; j++) { a0[j] = b; a1[j] = b; }
        const float* wc = ws + c * 25;
        #pragma unroll
        for (int i6 = 0; i6 < 6; i6++) {
            int iy = 2 * py + i6;            // input row, <= 27
            float4 xq[7];
            const float4* rp = (const float4*)(xs + iy * 28);
            #pragma unroll
            for (int j = 0; j < 7; j++) xq[j] = rp[j];
            const float* xr = (const float*)xq;
            if (i6 <= 4) {                   // contributes to conv row 2*py (ky=i6)
                #pragma unroll
                for (int kx = 0; kx < 5; kx++) {
                    float w = wc[i6 * 5 + kx];
                    #pragma unroll
                    for (int ox = 0; ox < 24; ox++) a0[ox] = fmaf(xr[ox + kx], w, a0[ox]);
                }
            }
            if (i6 >= 1) {                   // contributes to conv row 2*py+1 (ky=i6-1)
                #pragma unroll
                for (int kx = 0; kx < 5; kx++) {
                    float w = wc[(i6 - 1) * 5 + kx];
                    #pragma unroll
                    for (int ox = 0; ox < 24; ox++) a1[ox] = fmaf(xr[ox + kx], w, a1[ox]);
                }
            }
        }
        float rmax = 0.0f;
        float* hp = g_h1 + n * 9216 + c * 144 + py * 12;
        #pragma unroll
        for (int px = 0; px < 12; px++) {
            float v = fmaxf(fmaxf(a0[2 * px], a0[2 * px + 1]),
                            fmaxf(a1[2 * px], a1[2 * px + 1]));
            v = fmaxf(v, 0.0f);   // relu-then-pool == pool-then-relu
            hp[px] = v;
            rmax = fmaxf(rmax, v);
        }
        atomicMax(&smax[c], __float_as_uint(rmax));  // vals >= 0: bit order == fp order
    }
    __syncthreads();
    if (threadIdx.x < 64)
        atomicAdd(&g_stat2[threadIdx.x],
                  __uint_as_float(smax[threadIdx.x]) * (1.0f / 2048.0f));
}

// ---------------- kernel 4: conv2 effective params (padded layout) -----------
__global__ void w2_kernel(const float* __restrict__ w0, const float* __restrict__ wS2,
                          const float* __restrict__ wG, const float* __restrict__ weta,
                          const float* __restrict__ wM, const float* __restrict__ b0,
                          const float* __restrict__ bS2, const float* __restrict__ bG,
                          const float* __restrict__ beta) {
    int idx = blockIdx.x * 256 + threadIdx.x;
    const int NW = 64 * 64 * 28;
    if (idx < NW) {
        int j = idx % 28;
        int cc = idx / 28;       // co*64 + ci
        int ci = cc & 63;
        float v = 0.0f;
        if (j < 25) {
            int src = cc * 25 + j;   // == co*1600 + ci*25 + j
            float M = fmaxf(g_stat2[ci], wM[ci]);
            v = scinol(w0[src], wS2[src], wG[src], weta[src], M, wG[src] != 0.0f);
        }
        g_w2p[idx] = v;
    } else if (idx < NW + 64) {
        int j = idx - NW;
        g_b2[j] = scinol(b0[j], bS2[j], bG[j], beta[j], 1.0f, bG[j] != 0.0f);
    }
}

// ---------------- kernel 5: conv2 + relu + pool + stat3 (f32x2 packed) -------
// dyn smem: xsA[9216] (input tile), xsB[9216] (tile shifted by one element for
// odd-offset aligned pair loads), bias[64]
extern __shared__ float cs2[];
__global__ void __launch_bounds__(512) conv2_kernel() {
    float* xsA = cs2;
    float* xsB = cs2 + 9216;
    float* bsp = cs2 + 18432;
    int n = blockIdx.x;
    const float* h1 = g_h1 + n * 9216;
    for (int i = threadIdx.x; i < 9216; i += 512) {
        xsA[i] = h1[i];
        xsB[i] = (i + 1 < 9216) ? h1[i + 1] : 0.0f;
    }
    if (threadIdx.x < 64) bsp[threadIdx.x] = g_b2[threadIdx.x];
    __syncthreads();

    int co = threadIdx.x >> 3;       // 0..63
    int r  = threadIdx.x & 7;        // conv output row 0..7
    unsigned long long acc[4];       // packed pairs of the 8 outputs in this row
    {
        unsigned long long binit = pk2(bsp[co]);
        #pragma unroll
        for (int j = 0; j < 4; j++) acc[j] = binit;
    }
    const float4* wbase = ((const float4*)g_w2p) + co * 64 * 7;

    #pragma unroll 1
    for (int ci = 0; ci < 64; ci++) {
        float4 wv[7];
        #pragma unroll
        for (int j = 0; j < 7; j++) wv[j] = wbase[ci * 7 + j];
        const float* wr = (const float*)wv;
        const float* baseA = xsA + ci * 144 + r * 12;
        const float* baseB = xsB + ci * 144 + r * 12;
        #pragma unroll
        for (int ky = 0; ky < 5; ky++) {
            ulonglong2 eA0 = *(const ulonglong2*)(baseA + ky * 12);
            ulonglong2 eA1 = *(const ulonglong2*)(baseA + ky * 12 + 4);
            ulonglong2 eA2 = *(const ulonglong2*)(baseA + ky * 12 + 8);
            ulonglong2 eB0 = *(const ulonglong2*)(baseB + ky * 12);
            ulonglong2 eB1 = *(const ulonglong2*)(baseB + ky * 12 + 4);
            ulonglong2 eB2 = *(const ulonglong2*)(baseB + ky * 12 + 8);
            unsigned long long pe[6] = {eA0.x, eA0.y, eA1.x, eA1.y, eA2.x, eA2.y};
            unsigned long long po[5] = {eB0.x, eB0.y, eB1.x, eB1.y, eB2.x};
            #pragma unroll
            for (int kx = 0; kx < 5; kx++) {
                unsigned long long ww = pk2(wr[ky * 5 + kx]);
                if ((kx & 1) == 0) {
                    int h = kx >> 1;
                    fma2(acc[0], pe[h + 0], ww);
                    fma2(acc[1], pe[h + 1], ww);
                    fma2(acc[2], pe[h + 2], ww);
                    fma2(acc[3], pe[h + 3], ww);
                } else {
                    int h = kx >> 1;
                    fma2(acc[0], po[h + 0], ww);
                    fma2(acc[1], po[h + 1], ww);
                    fma2(acc[2], po[h + 2], ww);
                    fma2(acc[3], po[h + 3], ww);
                }
            }
        }
    }

    float out[8];
    upk2(acc[0], out[0], out[1]);
    upk2(acc[1], out[2], out[3]);
    upk2(acc[2], out[4], out[5]);
    upk2(acc[3], out[6], out[7]);
    float p[4];
    #pragma unroll
    for (int px = 0; px < 4; px++) p[px] = fmaxf(out[2 * px], out[2 * px + 1]);
    #pragma unroll
    for (int px = 0; px < 4; px++) {
        float o = __shfl_xor_sync(0xffffffffu, p[px], 1);  // partner conv row
        p[px] = fmaxf(fmaxf(p[px], o), 0.0f);
    }
    if ((r & 1) == 0) {
        int q = r >> 1;                      // pooled row 0..3
        int fb = co * 16 + q * 4;
        float* hp = g_h2 + n * 1024 + fb;
        #pragma unroll
        for (int px = 0; px < 4; px++) {
            hp[px] = p[px];
            atomicAdd(&g_stat3[fb + px], p[px] * (1.0f / 2048.0f));
        }
    }
}

// ---------------- kernel 6: linear effective params --------------------------
__global__ void wl_kernel(const float* __restrict__ w0, const float* __restrict__ wS2,
                          const float* __restrict__ wG, const float* __restrict__ weta,
                          const float* __restrict__ wM, const float* __restrict__ b0,
                          const float* __restrict__ bS2, const float* __restrict__ bG,
                          const float* __restrict__ beta) {
    int idx = blockIdx.x * 256 + threadIdx.x;
    if (idx < 10240) {
        int i = idx & 1023;
        float M = fmaxf(wM[idx], g_stat3[i]);
        // NOTE: linear weight cond is wS2 != 0 (not wG), per reference
        g_wl[idx] = scinol(w0[idx], wS2[idx], wG[idx], weta[idx], M, wS2[idx] != 0.0f);
    } else if (idx < 10250) {
        int j = idx - 10240;
        g_bl[j] = scinol(b0[j], bS2[j], bG[j], beta[j], 1.0f, bS2[j] != 0.0f);
    }
}

// ---------------- kernel 7: linear layer -------------------------------------
__global__ void __launch_bounds__(256) linear_kernel(float* __restrict__ out) {
    __shared__ float w_s[10240];
    __shared__ float b_s[16];
    for (int i = threadIdx.x; i < 10240; i += 256) w_s[i] = g_wl[i];
    if (threadIdx.x < 10) b_s[threadIdx.x] = g_bl[threadIdx.x];
    __syncthreads();
    int warp = threadIdx.x >> 5, lane = threadIdx.x & 31;
    for (int n = blockIdx.x * 8 + warp; n < 2048; n += 64 * 8) {
        const float* h = g_h2 + n * 1024;
        float hv[32];
        #pragma unroll
        for (int j = 0; j < 32; j++) hv[j] = h[lane + j * 32];
        #pragma unroll 1
        for (int o = 0; o < 10; o++) {
            float s = 0.0f;
            #pragma unroll
            for (int j = 0; j < 32; j++) s = fmaf(hv[j], w_s[o * 1024 + lane + j * 32], s);
            #pragma unroll
            for (int off = 16; off; off >>= 1) s += __shfl_xor_sync(0xffffffffu, s, off);
            if (lane == 0) out[n * 10 + o] = s + b_s[o];
        }
    }
}

// ---------------- launch ------------------------------------------------------
extern "C" void kernel_launch(void* const* d_in, const int* in_sizes, int n_in,
                              void* d_out, int out_size) {
    const float* x = (const float*)d_in[0];
    const float* c1[9]; for (int i = 0; i < 9; i++) c1[i] = (const float*)d_in[1 + i];
    const float* c2[9]; for (int i = 0; i < 9; i++) c2[i] = (const float*)d_in[10 + i];
    const float* lp[9]; for (int i = 0; i < 9; i++) lp[i] = (const float*)d_in[19 + i];
    float* out = (float*)d_out;

    const int conv2_smem = (9216 * 2 + 64) * sizeof(float);  // 73984 B
    cudaFuncSetAttribute(conv2_kernel, cudaFuncAttributeMaxDynamicSharedMemorySize,
                         conv2_smem);

    zero_stats_kernel<<<1, 1024>>>();
    stat1_kernel<<<2048, 256>>>(x);
    w1_kernel<<<7, 256>>>(c1[0], c1[1], c1[2], c1[3], c1[4], c1[5], c1[6], c1[7], c1[8]);
    conv1_kernel<<<2048, 256>>>(x);
    w2_kernel<<<449, 256>>>(c2[0], c2[1], c2[2], c2[3], c2[4], c2[5], c2[6], c2[7], c2[8]);
    conv2_kernel<<<2048, 512, conv2_smem>>>();
    wl_kernel<<<41, 256>>>(lp[0], lp[1], lp[2], lp[3], lp[4], lp[5], lp[6], lp[7], lp[8]);
    linear_kernel<<<64, 256>>>(out);
}

// round 3
// speedup vs baseline: 1.4103x; 1.4103x over previous
#include <cuda_runtime.h>

// ---------------- device scratch (allocation-free: __device__ globals) -------
__device__ float g_stat1;            // conv1 input stat (scalar, C_in=1)
__device__ float g_stat2[64];        // conv2 input stat per channel
__device__ float g_stat3[1024];      // linear input stat per feature
__device__ float g_w1[1600];         // conv1 effective weights (64,1,5,5)
__device__ float g_b1[64];
__device__ unsigned long long g_w2p2u[64 * 64 * 25]; // conv2 eff weights as splatted
                                                     // (w,w) pairs, idx = ci*1600+co*25+j
__device__ float g_b2[64];
__device__ float g_wl[10240];        // linear eff weights (10,1024)
__device__ float g_bl[10];
__device__ __align__(16) float g_h1[2048 * 64 * 144]; // pooled conv1 output (N,64,12,12)
__device__ __align__(16) float g_h2[2048 * 1024];     // pooled conv2 output (N,1024)

// ---------------- helpers ----------------------------------------------------
__device__ __forceinline__ float scinol(float p0, float S2, float G, float eta,
                                        float M, bool cond) {
    float denom = sqrtf(S2 + M * M);
    float theta = fminf(fmaxf(G / denom, -1.0f), 1.0f);
    float upd = cond ? theta / (2.0f * denom) * eta : 0.0f;
    return p0 + upd;
}

__device__ __forceinline__ unsigned long long pk2(float v) {
    unsigned long long r;
    asm("mov.b64 %0, {%1, %2};" : "=l"(r) : "f"(v), "f"(v));
    return r;
}
__device__ __forceinline__ void fma2(unsigned long long& d, unsigned long long a,
                                     unsigned long long b) {
    asm("fma.rn.f32x2 %0, %1, %2, %0;" : "+l"(d) : "l"(a), "l"(b));
}
__device__ __forceinline__ void upk2(unsigned long long v, float& lo, float& hi) {
    asm("mov.b64 {%0, %1}, %2;" : "=f"(lo), "=f"(hi) : "l"(v));
}

// ---------------- kernel 0: zero stat accumulators ---------------------------
__global__ void zero_stats_kernel() {
    int i = threadIdx.x;
    if (i == 0) g_stat1 = 0.0f;
    if (i < 64) g_stat2[i] = 0.0f;
    if (i < 1024) g_stat3[i] = 0.0f;
}

// ---------------- kernel 1: stat1 = mean_n max_hw |x| ------------------------
__global__ void stat1_kernel(const float* __restrict__ x) {
    int n = blockIdx.x;
    const float* xs = x + n * 784;
    float m = 0.0f;
    for (int i = threadIdx.x; i < 784; i += 256) m = fmaxf(m, fabsf(xs[i]));
    __shared__ float red[8];
    #pragma unroll
    for (int o = 16; o; o >>= 1) m = fmaxf(m, __shfl_xor_sync(0xffffffffu, m, o));
    if ((threadIdx.x & 31) == 0) red[threadIdx.x >> 5] = m;
    __syncthreads();
    if (threadIdx.x < 8) {
        m = red[threadIdx.x];
        #pragma unroll
        for (int o = 4; o; o >>= 1) m = fmaxf(m, __shfl_xor_sync(0x000000ffu, m, o));
        if (threadIdx.x == 0) atomicAdd(&g_stat1, m * (1.0f / 2048.0f));
    }
}

// ---------------- kernel 2: conv1 effective params ---------------------------
__global__ void w1_kernel(const float* __restrict__ w0, const float* __restrict__ wS2,
                          const float* __restrict__ wG, const float* __restrict__ weta,
                          const float* __restrict__ wM, const float* __restrict__ b0,
                          const float* __restrict__ bS2, const float* __restrict__ bG,
                          const float* __restrict__ beta) {
    int i = blockIdx.x * 256 + threadIdx.x;
    if (i < 1600) {
        float M = fmaxf(g_stat1, wM[0]);  // C_in = 1
        g_w1[i] = scinol(w0[i], wS2[i], wG[i], weta[i], M, wG[i] != 0.0f);
    } else if (i < 1664) {
        int j = i - 1600;
        g_b1[j] = scinol(b0[j], bS2[j], bG[j], beta[j], 1.0f, bG[j] != 0.0f);
    }
}

// ---------------- kernel 3: conv1 + relu + pool + stat2 ----------------------
__global__ void __launch_bounds__(256) conv1_kernel(const float* __restrict__ x) {
    __shared__ float xs[784];
    __shared__ float ws[1600];
    __shared__ float bs[64];
    __shared__ unsigned int smax[64];
    int n = blockIdx.x;
    const float* xp = x + n * 784;
    for (int i = threadIdx.x; i < 784; i += 256) xs[i] = xp[i];
    for (int i = threadIdx.x; i < 1600; i += 256) ws[i] = g_w1[i];
    if (threadIdx.x < 64) { bs[threadIdx.x] = g_b1[threadIdx.x]; smax[threadIdx.x] = 0u; }
    __syncthreads();

    #pragma unroll 1
    for (int it = 0; it < 3; it++) {
        int task = threadIdx.x + it * 256;   // 768 tasks = 64 ch * 12 pooled rows
        int c = task / 12;
        int py = task % 12;
        float a0[24], a1[24];
        float b = bs[c];
        #pragma unroll
        for (int j = 0; j < 24; j++) { a0[j] = b; a1[j] = b; }
        const float* wc = ws + c * 25;
        #pragma unroll
        for (int i6 = 0; i6 < 6; i6++) {
            int iy = 2 * py + i6;            // input row, <= 27
            float4 xq[7];
            const float4* rp = (const float4*)(xs + iy * 28);
            #pragma unroll
            for (int j = 0; j < 7; j++) xq[j] = rp[j];
            const float* xr = (const float*)xq;
            if (i6 <= 4) {                   // conv row 2*py (ky=i6)
                #pragma unroll
                for (int kx = 0; kx < 5; kx++) {
                    float w = wc[i6 * 5 + kx];
                    #pragma unroll
                    for (int ox = 0; ox < 24; ox++) a0[ox] = fmaf(xr[ox + kx], w, a0[ox]);
                }
            }
            if (i6 >= 1) {                   // conv row 2*py+1 (ky=i6-1)
                #pragma unroll
                for (int kx = 0; kx < 5; kx++) {
                    float w = wc[(i6 - 1) * 5 + kx];
                    #pragma unroll
                    for (int ox = 0; ox < 24; ox++) a1[ox] = fmaf(xr[ox + kx], w, a1[ox]);
                }
            }
        }
        float rmax = 0.0f;
        float* hp = g_h1 + n * 9216 + c * 144 + py * 12;
        #pragma unroll
        for (int px = 0; px < 12; px++) {
            float v = fmaxf(fmaxf(a0[2 * px], a0[2 * px + 1]),
                            fmaxf(a1[2 * px], a1[2 * px + 1]));
            v = fmaxf(v, 0.0f);   // relu-then-pool == pool-then-relu
            hp[px] = v;
            rmax = fmaxf(rmax, v);
        }
        atomicMax(&smax[c], __float_as_uint(rmax));  // vals >= 0: bit order == fp order
    }
    __syncthreads();
    if (threadIdx.x < 64)
        atomicAdd(&g_stat2[threadIdx.x],
                  __uint_as_float(smax[threadIdx.x]) * (1.0f / 2048.0f));
}

// ---------------- kernel 4: conv2 effective params (ci-major splatted pairs) -
__global__ void w2_kernel(const float* __restrict__ w0, const float* __restrict__ wS2,
                          const float* __restrict__ wG, const float* __restrict__ weta,
                          const float* __restrict__ wM, const float* __restrict__ b0,
                          const float* __restrict__ bS2, const float* __restrict__ bG,
                          const float* __restrict__ beta) {
    int idx = blockIdx.x * 256 + threadIdx.x;
    const int NW = 64 * 64 * 25;
    if (idx < NW) {
        // dst idx = ci*1600 + co*25 + j
        int j = idx % 25;
        int t = idx / 25;        // ci*64 + co
        int co = t & 63;
        int ci = t >> 6;
        int src = co * 1600 + ci * 25 + j;
        float M = fmaxf(g_stat2[ci], wM[ci]);
        float v = scinol(w0[src], wS2[src], wG[src], weta[src], M, wG[src] != 0.0f);
        float2 p; p.x = v; p.y = v;
        ((float2*)g_w2p2u)[idx] = p;
    } else if (idx < NW + 64) {
        int j = idx - NW;
        g_b2[j] = scinol(b0[j], bS2[j], bG[j], beta[j], 1.0f, bG[j] != 0.0f);
    }
}

// ---------------- kernel 5: conv2 + relu + pool + stat3 ----------------------
// CTA = 2 samples, 512 threads. warp = (sample, row-pair q, co-half); lane = co.
// x loads are warp-broadcast (all lanes same address) -> ~free on the smem
// crossbar; weights staged per-2-ci into a double-buffered smem ring as
// pre-splatted (w,w) 64-bit pairs, prefetched through registers.
// dyn smem: xsA[2][9216] + xsB[2][9216] (one-elem-shifted) + wbuf[2][3200] ull
extern __shared__ float cs2[];
__global__ void __launch_bounds__(512) conv2_kernel() {
    float* xsA = cs2;                                   // 2*9216 floats
    float* xsB = cs2 + 18432;                           // 2*9216 floats
    unsigned long long* wbuf = (unsigned long long*)(cs2 + 36864);  // 2*3200 ull
    int tid = threadIdx.x;
    int n0 = blockIdx.x * 2;

    #pragma unroll
    for (int s = 0; s < 2; s++) {
        const float* h1 = g_h1 + (n0 + s) * 9216;
        float* xa = xsA + s * 9216;
        float* xb = xsB + s * 9216;
        for (int i = tid; i < 2304; i += 512)
            ((float4*)xa)[i] = ((const float4*)h1)[i];
        for (int i = tid; i < 9216; i += 512)
            xb[i] = (i < 9215) ? h1[i + 1] : 0.0f;
    }

    int w = tid >> 5, lane = tid & 31;
    int s = w >> 3;            // sample within CTA
    int q = (w >> 1) & 3;      // pooled row pair: conv rows 2q, 2q+1
    int ch = w & 1;            // co half
    int co = ch * 32 + lane;

    const float* xa = xsA + s * 9216 + q * 24;
    const float* xb = xsB + s * 9216 + q * 24;

    unsigned long long a0[4], a1[4];
    {
        unsigned long long bi = pk2(g_b2[co]);
        #pragma unroll
        for (int j = 0; j < 4; j++) { a0[j] = bi; a1[j] = bi; }
    }

    // prologue: stage-0 weight pairs into registers
    unsigned long long wreg[7];
    #pragma unroll
    for (int k = 0; k < 7; k++) {
        int id = tid + k * 512;
        if (id < 3200) wreg[k] = g_w2p2u[id];
    }

    #pragma unroll 1
    for (int st = 0; st < 32; st++) {
        unsigned long long* wb = wbuf + (st & 1) * 3200;
        #pragma unroll
        for (int k = 0; k < 7; k++) {
            int id = tid + k * 512;
            if (id < 3200) wb[id] = wreg[k];
        }
        __syncthreads();
        if (st < 31) {
            const unsigned long long* gw = g_w2p2u + (st + 1) * 3200;
            #pragma unroll
            for (int k = 0; k < 7; k++) {
                int id = tid + k * 512;
                if (id < 3200) wreg[k] = gw[id];
            }
        }
        #pragma unroll
        for (int ciL = 0; ciL < 2; ciL++) {
            int ci = st * 2 + ciL;
            const unsigned long long* wp = wb + ciL * 1600 + co * 25;
            const float* bA = xa + ci * 144;
            const float* bB = xb + ci * 144;
            unsigned long long wprev[5];
            #pragma unroll
            for (int ir = 0; ir < 6; ir++) {
                ulonglong2 eA0 = *(const ulonglong2*)(bA + ir * 12);
                ulonglong2 eA1 = *(const ulonglong2*)(bA + ir * 12 + 4);
                ulonglong2 eA2 = *(const ulonglong2*)(bA + ir * 12 + 8);
                ulonglong2 eB0 = *(const ulonglong2*)(bB + ir * 12);
                ulonglong2 eB1 = *(const ulonglong2*)(bB + ir * 12 + 4);
                unsigned long long eB2x = *(const unsigned long long*)(bB + ir * 12 + 8);
                unsigned long long pe[6] = {eA0.x, eA0.y, eA1.x, eA1.y, eA2.x, eA2.y};
                unsigned long long po[5] = {eB0.x, eB0.y, eB1.x, eB1.y, eB2x};
                unsigned long long wcur[5];
                if (ir <= 4) {
                    #pragma unroll
                    for (int kx = 0; kx < 5; kx++) wcur[kx] = wp[ir * 5 + kx];
                    #pragma unroll
                    for (int kx = 0; kx < 5; kx++) {
                        int h = kx >> 1;
                        const unsigned long long* src = (kx & 1) ? po : pe;
                        fma2(a0[0], src[h + 0], wcur[kx]);
                        fma2(a0[1], src[h + 1], wcur[kx]);
                        fma2(a0[2], src[h + 2], wcur[kx]);
                        fma2(a0[3], src[h + 3], wcur[kx]);
                    }
                }
                if (ir >= 1) {
                    #pragma unroll
                    for (int kx = 0; kx < 5; kx++) {
                        int h = kx >> 1;
                        const unsigned long long* src = (kx & 1) ? po : pe;
                        fma2(a1[0], src[h + 0], wprev[kx]);
                        fma2(a1[1], src[h + 1], wprev[kx]);
                        fma2(a1[2], src[h + 2], wprev[kx]);
                        fma2(a1[3], src[h + 3], wprev[kx]);
                    }
                }
                #pragma unroll
                for (int kx = 0; kx < 5; kx++) wprev[kx] = wcur[kx];
            }
        }
    }

    // epilogue: 2x2 pool + relu entirely in-thread
    #pragma unroll
    for (int j = 0; j < 4; j++) {
        float r0lo, r0hi, r1lo, r1hi;
        upk2(a0[j], r0lo, r0hi);
        upk2(a1[j], r1lo, r1hi);
        float p = fmaxf(fmaxf(r0lo, r0hi), fmaxf(r1lo, r1hi));
        p = fmaxf(p, 0.0f);
        int fb = co * 16 + q * 4 + j;
        g_h2[(n0 + s) * 1024 + fb] = p;
        atomicAdd(&g_stat3[fb], p * (1.0f / 2048.0f));
    }
}

// ---------------- kernel 6: linear effective params --------------------------
__global__ void wl_kernel(const float* __restrict__ w0, const float* __restrict__ wS2,
                          const float* __restrict__ wG, const float* __restrict__ weta,
                          const float* __restrict__ wM, const float* __restrict__ b0,
                          const float* __restrict__ bS2, const float* __restrict__ bG,
                          const float* __restrict__ beta) {
    int idx = blockIdx.x * 256 + threadIdx.x;
    if (idx < 10240) {
        int i = idx & 1023;
        float M = fmaxf(wM[idx], g_stat3[i]);
        // NOTE: linear weight cond is wS2 != 0 (not wG), per reference
        g_wl[idx] = scinol(w0[idx], wS2[idx], wG[idx], weta[idx], M, wS2[idx] != 0.0f);
    } else if (idx < 10250) {
        int j = idx - 10240;
        g_bl[j] = scinol(b0[j], bS2[j], bG[j], beta[j], 1.0f, bS2[j] != 0.0f);
    }
}

// ---------------- kernel 7: linear layer -------------------------------------
__global__ void __launch_bounds__(256) linear_kernel(float* __restrict__ out) {
    __shared__ float w_s[10240];
    __shared__ float b_s[16];
    for (int i = threadIdx.x; i < 10240; i += 256) w_s[i] = g_wl[i];
    if (threadIdx.x < 10) b_s[threadIdx.x] = g_bl[threadIdx.x];
    __syncthreads();
    int warp = threadIdx.x >> 5, lane = threadIdx.x & 31;
    for (int n = blockIdx.x * 8 + warp; n < 2048; n += 64 * 8) {
        const float* h = g_h2 + n * 1024;
        float hv[32];
        #pragma unroll
        for (int j = 0; j < 32; j++) hv[j] = h[lane + j * 32];
        #pragma unroll 1
        for (int o = 0; o < 10; o++) {
            float s = 0.0f;
            #pragma unroll
            for (int j = 0; j < 32; j++) s = fmaf(hv[j], w_s[o * 1024 + lane + j * 32], s);
            #pragma unroll
            for (int off = 16; off; off >>= 1) s += __shfl_xor_sync(0xffffffffu, s, off);
            if (lane == 0) out[n * 10 + o] = s + b_s[o];
        }
    }
}

// ---------------- launch ------------------------------------------------------
extern "C" void kernel_launch(void* const* d_in, const int* in_sizes, int n_in,
                              void* d_out, int out_size) {
    const float* x = (const float*)d_in[0];
    const float* c1[9]; for (int i = 0; i < 9; i++) c1[i] = (const float*)d_in[1 + i];
    const float* c2[9]; for (int i = 0; i < 9; i++) c2[i] = (const float*)d_in[10 + i];
    const float* lp[9]; for (int i = 0; i < 9; i++) lp[i] = (const float*)d_in[19 + i];
    float* out = (float*)d_out;

    // xsA + xsB (2 samples each) + double-buffered weight ring
    const int conv2_smem = 36864 * 4 + 2 * 3200 * 8;  // 198656 B
    cudaFuncSetAttribute(conv2_kernel, cudaFuncAttributeMaxDynamicSharedMemorySize,
                         conv2_smem);

    zero_stats_kernel<<<1, 1024>>>();
    stat1_kernel<<<2048, 256>>>(x);
    w1_kernel<<<7, 256>>>(c1[0], c1[1], c1[2], c1[3], c1[4], c1[5], c1[6], c1[7], c1[8]);
    conv1_kernel<<<2048, 256>>>(x);
    w2_kernel<<<401, 256>>>(c2[0], c2[1], c2[2], c2[3], c2[4], c2[5], c2[6], c2[7], c2[8]);
    conv2_kernel<<<1024, 512, conv2_smem>>>();
    wl_kernel<<<41, 256>>>(lp[0], lp[1], lp[2], lp[3], lp[4], lp[5], lp[6], lp[7], lp[8]);
    linear_kernel<<<64, 256>>>(out);
}